// round 1
// baseline (speedup 1.0000x reference)
#include <cuda_runtime.h>
#include <cstdint>
#include <cstddef>

// Residual VQ: N=16384 rows, DIM=512, KS=4096 codes, DEPTH=4 (read from input).
//
// Strategy (R0): fully fused per-row pipeline. Each CTA owns 32 rows; residual
// lives in SMEM across all depths. Codebook (8MB, L2-resident) is streamed as
// packed float2 k-pairs so the inner product uses Blackwell packed fp32x2 FMA
// (fma.rn.f32x2) for 2x fp32 throughput. Argmax fused into the sweep with
// jnp.argmax tie-breaking (lowest index). total = x - residual_final.

#define N_ROWS   16384
#define DIM      512
#define KS       4096
#define KP       (DIM / 2)            // 256 float2 k-pairs per vector
#define ROWS     32                   // rows per CTA
#define THREADS  256
#define NWARPS   (THREADS / 32)       // 8
#define CODES_PER_WARP (KS / NWARPS)  // 512
#define NGROUPS  (CODES_PER_WARP / 32) // 16

// Packed codebook: element [kp][j] = (cb[j][2kp], cb[j][2kp+1]) as one 64-bit
// value. Layout [KP][KS] so a warp's 32 lanes (consecutive codes) load 256B
// contiguous per k-pair.
__device__ unsigned long long g_cb2[(size_t)KP * KS];

// ---------------------------------------------------------------------------
// Kernel 1: pack/transpose the codebook (runs every launch; idempotent).
// ---------------------------------------------------------------------------
__global__ void pack_codebook_kernel(const float* __restrict__ cb) {
    __shared__ float2 tile[32][33];
    const int c0  = blockIdx.x * 32;   // code tile base
    const int kp0 = blockIdx.y * 32;   // k-pair tile base
    const int tx = threadIdx.x;        // 0..31
    const int ty = threadIdx.y;        // 0..7
#pragma unroll
    for (int i = 0; i < 4; i++) {
        const int c  = c0 + ty + 8 * i;
        const int kp = kp0 + tx;
        const float2* row = reinterpret_cast<const float2*>(cb + (size_t)c * DIM);
        tile[ty + 8 * i][tx] = row[kp];   // coalesced read
    }
    __syncthreads();
#pragma unroll
    for (int i = 0; i < 4; i++) {
        const int kp = kp0 + ty + 8 * i;
        const int c  = c0 + tx;
        const float2 v = tile[tx][ty + 8 * i];
        unsigned long long u;
        asm("mov.b64 %0, {%1, %2};" : "=l"(u) : "f"(v.x), "f"(v.y));
        g_cb2[(size_t)kp * KS + c] = u;   // coalesced write across codes
    }
}

// ---------------------------------------------------------------------------
// Packed fp32x2 helpers (Blackwell sm_100+)
// ---------------------------------------------------------------------------
__device__ __forceinline__ unsigned long long ffma2(unsigned long long a,
                                                    unsigned long long b,
                                                    unsigned long long c) {
    unsigned long long d;
    asm("fma.rn.f32x2 %0, %1, %2, %3;" : "=l"(d) : "l"(a), "l"(b), "l"(c));
    return d;
}

__device__ __forceinline__ float lo_plus_hi(unsigned long long v) {
    float x, y;
    asm("mov.b64 {%0, %1}, %2;" : "=f"(x), "=f"(y) : "l"(v));
    return x + y;
}

// ---------------------------------------------------------------------------
// Kernel 2: fused RVQ. grid = N_ROWS/ROWS = 512 CTAs, 256 threads.
// Dynamic SMEM: ROWS*DIM floats (64 KB) for the residual block.
// ---------------------------------------------------------------------------
extern __shared__ __align__(16) float s_res[];   // [ROWS][DIM]

__global__ void __launch_bounds__(THREADS, 2)
rvq_kernel(const float* __restrict__ x, const float* __restrict__ cb,
           const int* __restrict__ depth_ptr, float* __restrict__ out) {
    __shared__ float s_bv[NWARPS][ROWS];
    __shared__ int   s_bi[NWARPS][ROWS];
    __shared__ float s_u[ROWS];
    __shared__ int   s_arg[ROWS];

    const int tid  = threadIdx.x;
    const int warp = tid >> 5;
    const int lane = tid & 31;
    const size_t row0 = (size_t)blockIdx.x * ROWS;

    int depth = 4;
    if (depth_ptr) {
        const int d = *depth_ptr;       // int32 scalar input (also correct if int64 LE)
        if (d >= 0 && d <= 32) depth = d;
    }

    // Load residual = x rows (coalesced float4).
    const float4* x4 = reinterpret_cast<const float4*>(x + row0 * DIM);
    float4* s4 = reinterpret_cast<float4*>(s_res);
    for (int i = tid; i < ROWS * DIM / 4; i += THREADS) s4[i] = x4[i];
    __syncthreads();

    for (int d = 0; d < depth; d++) {
        // Per-lane running best: lane r owns row r.
        float best_v = -3.0e38f;
        int   best_i = 0x7fffffff;

        // --- codebook sweep: warp covers CODES_PER_WARP codes, 32 at a time ---
        for (int g = 0; g < NGROUPS; g++) {
            const int code = (warp * NGROUPS + g) * 32 + lane;
            const unsigned long long* cbp = g_cb2 + code;

            unsigned long long acc[ROWS];
#pragma unroll
            for (int r = 0; r < ROWS; r++) acc[r] = 0ull;

#pragma unroll 2
            for (int kp = 0; kp < KP; kp += 2) {
                const unsigned long long c0 = cbp[(size_t)kp * KS];
                const unsigned long long c1 = cbp[(size_t)(kp + 1) * KS];
#pragma unroll
                for (int r = 0; r < ROWS; r++) {
                    // 4 consecutive k-values of row r: two packed pairs (16B, broadcast LDS)
                    const ulonglong2 rr =
                        *reinterpret_cast<const ulonglong2*>(&s_res[r * DIM + 2 * kp]);
                    acc[r] = ffma2(rr.x, c0, acc[r]);
                    acc[r] = ffma2(rr.y, c1, acc[r]);
                }
            }

            // Per-row warp argmax (tie-break: lowest code index, matches jnp.argmax).
#pragma unroll 4
            for (int r = 0; r < ROWS; r++) {
                float v  = lo_plus_hi(acc[r]);
                int  idx = code;
#pragma unroll
                for (int off = 16; off > 0; off >>= 1) {
                    const float ov = __shfl_xor_sync(0xffffffffu, v, off);
                    const int   oi = __shfl_xor_sync(0xffffffffu, idx, off);
                    if (ov > v || (ov == v && oi < idx)) { v = ov; idx = oi; }
                }
                if (lane == r) {
                    if (v > best_v || (v == best_v && idx < best_i)) {
                        best_v = v; best_i = idx;
                    }
                }
            }
        }

        // Cross-warp merge.
        s_bv[warp][lane] = best_v;
        s_bi[warp][lane] = best_i;
        __syncthreads();
        if (warp == 0) {
            float v  = s_bv[0][lane];
            int  idx = s_bi[0][lane];
#pragma unroll
            for (int w = 1; w < NWARPS; w++) {
                const float ov = s_bv[w][lane];
                const int   oi = s_bi[w][lane];
                if (ov > v || (ov == v && oi < idx)) { v = ov; idx = oi; }
            }
            s_u[lane]   = v;     // u = max inner product (exact fp32 accumulation)
            s_arg[lane] = idx;
        }
        __syncthreads();

        // residual[r] -= u[r] * codebook[arg[r]]  (each warp updates ROWS/NWARPS rows)
#pragma unroll
        for (int rr = 0; rr < ROWS / NWARPS; rr++) {
            const int r = warp * (ROWS / NWARPS) + rr;
            const float u = s_u[r];
            const float4* crow =
                reinterpret_cast<const float4*>(cb + (size_t)s_arg[r] * DIM);
            float4* rrow = reinterpret_cast<float4*>(&s_res[r * DIM]);
#pragma unroll
            for (int k4 = 0; k4 < DIM / 4 / 32; k4++) {
                const int j = lane + 32 * k4;
                const float4 c = crow[j];
                float4 v = rrow[j];
                v.x -= u * c.x; v.y -= u * c.y; v.z -= u * c.z; v.w -= u * c.w;
                rrow[j] = v;
            }
        }
        __syncthreads();
    }

    // total = x - residual_final (exact identity: total accumulates what residual loses)
    float4* o4 = reinterpret_cast<float4*>(out + row0 * DIM);
    for (int i = tid; i < ROWS * DIM / 4; i += THREADS) {
        const float4 xv = x4[i];
        const float4 rv = s4[i];
        o4[i] = make_float4(xv.x - rv.x, xv.y - rv.y, xv.z - rv.z, xv.w - rv.w);
    }
}

// ---------------------------------------------------------------------------
extern "C" void kernel_launch(void* const* d_in, const int* in_sizes, int n_in,
                              void* d_out, int out_size) {
    const float* x  = (const float*)d_in[0];
    const float* cb = (const float*)d_in[1];
    const int* depth_ptr = (n_in > 2) ? (const int*)d_in[2] : nullptr;
    float* out = (float*)d_out;

    // 64 KB dynamic smem needs the opt-in attribute (not an allocation;
    // executes immediately, safe under graph capture). Idempotent per call.
    cudaFuncSetAttribute(rvq_kernel, cudaFuncAttributeMaxDynamicSharedMemorySize,
                         ROWS * DIM * (int)sizeof(float));

    dim3 pg(KS / 32, KP / 32);
    dim3 pb(32, 8);
    pack_codebook_kernel<<<pg, pb>>>(cb);

    rvq_kernel<<<N_ROWS / ROWS, THREADS, ROWS * DIM * sizeof(float)>>>(
        x, cb, depth_ptr, out);
}

// round 2
// speedup vs baseline: 2.3807x; 2.3807x over previous
#include <cuda_runtime.h>
#include <cstdint>
#include <cstddef>

// Residual VQ, round 2: SGEMM-style register blocking.
// ip = residual[32x512] @ cb^T[512x4096], fused argmax, DEPTH=4.
//
// R1 was smem-crossbar bound (L1=77.6%, fma=22%): 1 broadcast LDS per 2 FFMA2.
// R2 inner loop: per thread 8 rows x 4 codes accumulators, packed over k
// (fma.rn.f32x2 with both operands natural u64 pairs from float4 loads, no
// dup MOVs). Codebook staged via 3-stage cp.async pipeline. Crossbar demand
// ~0.75 wf/cyc -> FMA pipe becomes the binder (~4.4ms floor measured from R1).

#define DIM      512
#define KS       4096
#define N_ROWS   16384
#define ROWS     32            // rows per CTA
#define THREADS  256
#define TM       8             // rows per thread
#define TN       4             // codes per thread (strided by 32 lanes)
#define BN       256           // codes per CTA sweep block (2 halves of 128)
#define BK       32            // k per stage
#define NSTAGE   3
#define QPS      (BK / 4)      // k-quads per stage = 8
#define NBLOCKS  (KS / BN)     // 16
#define KSTAGES  (DIM / BK)    // 16
#define TOTSTAGES (NBLOCKS * KSTAGES)  // 256 per depth
#define STAGE_E  (QPS * BN)    // 2048 float4 per stage

// Packed codebook: g_cbq[q * KS + c] = float4(cb[c][4q], cb[c][4q+1], cb[c][4q+2], cb[c][4q+3])
// Layout [DIM/4][KS] so a stage tile row (fixed q, 256 codes) is contiguous.
__device__ float4 g_cbq[(size_t)(DIM / 4) * KS];

// ---------------------------------------------------------------------------
// Pack kernel: transpose codebook into k-quad-major float4 layout.
// grid (KS/32, (DIM/4)/32) = (128, 4), block (32, 8).
// ---------------------------------------------------------------------------
__global__ void pack_codebook_kernel(const float* __restrict__ cb) {
    __shared__ float4 tile[32][33];
    const int c0 = blockIdx.x * 32;   // code tile base
    const int q0 = blockIdx.y * 32;   // k-quad tile base
    const int tx = threadIdx.x;       // 0..31
    const int ty = threadIdx.y;       // 0..7
    const float4* cb4 = reinterpret_cast<const float4*>(cb);
#pragma unroll
    for (int i = 0; i < 4; i++) {
        const int c = c0 + ty + 8 * i;
        tile[ty + 8 * i][tx] = cb4[(size_t)c * (DIM / 4) + q0 + tx];  // coalesced
    }
    __syncthreads();
#pragma unroll
    for (int i = 0; i < 4; i++) {
        const int q = q0 + ty + 8 * i;
        g_cbq[(size_t)q * KS + c0 + tx] = tile[tx][ty + 8 * i];       // coalesced
    }
}

// ---------------------------------------------------------------------------
// Packed fp32x2 helpers (Blackwell sm_100+)
// ---------------------------------------------------------------------------
__device__ __forceinline__ unsigned long long ffma2(unsigned long long a,
                                                    unsigned long long b,
                                                    unsigned long long c) {
    unsigned long long d;
    asm("fma.rn.f32x2 %0, %1, %2, %3;" : "=l"(d) : "l"(a), "l"(b), "l"(c));
    return d;
}

__device__ __forceinline__ float lo_plus_hi(unsigned long long v) {
    float x, y;
    asm("mov.b64 {%0, %1}, %2;" : "=f"(x), "=f"(y) : "l"(v));
    return x + y;
}

__device__ __forceinline__ void cp_async16(void* smem_dst, const void* gmem_src) {
    unsigned s = (unsigned)__cvta_generic_to_shared(smem_dst);
    asm volatile("cp.async.cg.shared.global [%0], [%1], 16;" :: "r"(s), "l"(gmem_src));
}
__device__ __forceinline__ void cp_commit() {
    asm volatile("cp.async.commit_group;");
}
__device__ __forceinline__ void cp_wait1() {
    asm volatile("cp.async.wait_group 1;");
}
__device__ __forceinline__ void cp_wait0() {
    asm volatile("cp.async.wait_group 0;");
}

// ---------------------------------------------------------------------------
// Main fused RVQ kernel. grid = 512, block = 256.
// Dynamic smem: 64KB residual + 3*32KB cb stages = 160KB -> 1 CTA/SM.
// ---------------------------------------------------------------------------
__global__ void __launch_bounds__(THREADS)
rvq_kernel(const float* __restrict__ x, const float* __restrict__ cb,
           const int* __restrict__ depth_ptr, float* __restrict__ out) {
    extern __shared__ __align__(16) unsigned char dynsmem[];
    float*      s_r  = reinterpret_cast<float*>(dynsmem);                 // [32][512]
    float4*     s_cb = reinterpret_cast<float4*>(dynsmem + ROWS * DIM * 4); // 3 stages [QPS][BN]

    __shared__ float s_bv[8][TM];
    __shared__ int   s_bi[8][TM];
    __shared__ float s_u[ROWS];
    __shared__ int   s_arg[ROWS];

    const int tid   = threadIdx.x;
    const int warp  = tid >> 5;
    const int lane  = tid & 31;
    const int trow  = warp & 3;   // row group: rows trow*8 .. trow*8+7
    const int chalf = warp >> 2;  // code half: 0 -> codes c0+0..127, 1 -> c0+128..255
    const size_t row0 = (size_t)blockIdx.x * ROWS;

    int depth = 4;
    if (depth_ptr) {
        const int d = *depth_ptr;
        if (d >= 0 && d <= 32) depth = d;
    }

    // Load residual = x rows (coalesced float4).
    const float4* x4 = reinterpret_cast<const float4*>(x + row0 * DIM);
    float4* s4 = reinterpret_cast<float4*>(s_r);
    for (int i = tid; i < ROWS * DIM / 4; i += THREADS) s4[i] = x4[i];
    __syncthreads();

    // Per-thread copy slice for a stage (8 x 16B per thread).
    // Stage s covers k-quads kq0..kq0+7 (kq0 = (s&15)*8) and codes c0..c0+255.
    auto copy_stage = [&](int s) {
        const int kq0 = (s & (KSTAGES - 1)) * QPS;
        const int c0  = (s >> 4) * BN;
        float4* dst = s_cb + (s % NSTAGE) * STAGE_E;
        const float4* src = g_cbq + (size_t)kq0 * KS + c0;
#pragma unroll
        for (int j = 0; j < 8; j++) {
            const int e = tid + THREADS * j;   // e = q*256 + c
            const int q = e >> 8;
            const int c = e & (BN - 1);
            cp_async16(dst + e, src + (size_t)q * KS + c);
        }
    };

    for (int d = 0; d < depth; d++) {
        unsigned long long acc[TM][TN];
#pragma unroll
        for (int i = 0; i < TM; i++)
#pragma unroll
            for (int j = 0; j < TN; j++) acc[i][j] = 0ull;

        float rb_v[TM];
        int   rb_i[TM];
#pragma unroll
        for (int i = 0; i < TM; i++) { rb_v[i] = -3.0e38f; rb_i[i] = 0x7fffffff; }

        // Pipeline prologue: stages 0, 1.
        copy_stage(0); cp_commit();
        copy_stage(1); cp_commit();

        for (int s = 0; s < TOTSTAGES; s++) {
            cp_wait1();          // stage s resident
            __syncthreads();     // all warps past compute(s-1); safe to reuse its buffer
            if (s + 2 < TOTSTAGES) copy_stage(s + 2);
            cp_commit();         // (empty group near the end is fine)

            // ---- compute stage s: 8 k-quads ----
            const unsigned long long* cbs = reinterpret_cast<const unsigned long long*>(
                s_cb + (s % NSTAGE) * STAGE_E + chalf * 128 + lane);
            const float* ar = s_r + (trow * TM) * DIM + (s & (KSTAGES - 1)) * BK;
#pragma unroll
            for (int q = 0; q < QPS; q++) {
                // codes: lane + 32*j (within this half), 16B of 4 k-values each
                const ulonglong2 b0 = *reinterpret_cast<const ulonglong2*>(cbs + (size_t)q * 512 + 0);
                const ulonglong2 b1 = *reinterpret_cast<const ulonglong2*>(cbs + (size_t)q * 512 + 64);
                const ulonglong2 b2 = *reinterpret_cast<const ulonglong2*>(cbs + (size_t)q * 512 + 128);
                const ulonglong2 b3 = *reinterpret_cast<const ulonglong2*>(cbs + (size_t)q * 512 + 192);
#pragma unroll
                for (int i = 0; i < TM; i++) {
                    const ulonglong2 a = *reinterpret_cast<const ulonglong2*>(ar + i * DIM + q * 4);
                    acc[i][0] = ffma2(a.x, b0.x, acc[i][0]);
                    acc[i][0] = ffma2(a.y, b0.y, acc[i][0]);
                    acc[i][1] = ffma2(a.x, b1.x, acc[i][1]);
                    acc[i][1] = ffma2(a.y, b1.y, acc[i][1]);
                    acc[i][2] = ffma2(a.x, b2.x, acc[i][2]);
                    acc[i][2] = ffma2(a.y, b2.y, acc[i][2]);
                    acc[i][3] = ffma2(a.x, b3.x, acc[i][3]);
                    acc[i][3] = ffma2(a.y, b3.y, acc[i][3]);
                }
            }

            // ---- block epilogue: full k swept for this 256-code block ----
            if ((s & (KSTAGES - 1)) == (KSTAGES - 1)) {
                const int cbase = (s >> 4) * BN + chalf * 128 + lane;
#pragma unroll
                for (int i = 0; i < TM; i++) {
                    float v  = lo_plus_hi(acc[i][0]);
                    int  idx = cbase;
#pragma unroll
                    for (int j = 1; j < TN; j++) {
                        const float fv = lo_plus_hi(acc[i][j]);
                        if (fv > v) { v = fv; idx = cbase + 32 * j; }  // idx ascending: strict >
                    }
#pragma unroll
                    for (int off = 16; off > 0; off >>= 1) {
                        const float ov = __shfl_xor_sync(0xffffffffu, v, off);
                        const int   oi = __shfl_xor_sync(0xffffffffu, idx, off);
                        if (ov > v || (ov == v && oi < idx)) { v = ov; idx = oi; }
                    }
                    if (v > rb_v[i] || (v == rb_v[i] && idx < rb_i[i])) {
                        rb_v[i] = v; rb_i[i] = idx;
                    }
                    acc[i][0] = 0ull; acc[i][1] = 0ull; acc[i][2] = 0ull; acc[i][3] = 0ull;
                }
            }
        }
        cp_wait0();   // drain (all real copies already consumed)

        // ---- depth end: merge warp-pair bests, update residual ----
        if (lane == 0) {
#pragma unroll
            for (int i = 0; i < TM; i++) { s_bv[warp][i] = rb_v[i]; s_bi[warp][i] = rb_i[i]; }
        }
        __syncthreads();
        if (tid < ROWS) {
            const int r = tid, tr = r >> 3, ri = r & 7;
            float v  = s_bv[tr][ri];
            int  idx = s_bi[tr][ri];
            const float ov = s_bv[tr + 4][ri];
            const int   oi = s_bi[tr + 4][ri];
            if (ov > v || (ov == v && oi < idx)) { v = ov; idx = oi; }
            s_u[r] = v; s_arg[r] = idx;
        }
        __syncthreads();

        // residual[r] -= u[r] * cb[arg[r]]; warp w handles rows w, w+8, w+16, w+24
#pragma unroll
        for (int rr = 0; rr < 4; rr++) {
            const int r = warp + rr * 8;
            const float u = s_u[r];
            const float4* crow = reinterpret_cast<const float4*>(cb + (size_t)s_arg[r] * DIM);
            float4* rrow = reinterpret_cast<float4*>(s_r + r * DIM);
#pragma unroll
            for (int t = 0; t < 4; t++) {
                const int k4 = lane + 32 * t;
                const float4 c4 = crow[k4];
                float4 v4 = rrow[k4];
                v4.x -= u * c4.x; v4.y -= u * c4.y; v4.z -= u * c4.z; v4.w -= u * c4.w;
                rrow[k4] = v4;
            }
        }
        __syncthreads();
    }

    // total = x - residual_final
    float4* o4 = reinterpret_cast<float4*>(out + row0 * DIM);
    for (int i = tid; i < ROWS * DIM / 4; i += THREADS) {
        const float4 xv = x4[i];
        const float4 rv = s4[i];
        o4[i] = make_float4(xv.x - rv.x, xv.y - rv.y, xv.z - rv.z, xv.w - rv.w);
    }
}

// ---------------------------------------------------------------------------
extern "C" void kernel_launch(void* const* d_in, const int* in_sizes, int n_in,
                              void* d_out, int out_size) {
    const float* x  = (const float*)d_in[0];
    const float* cb = (const float*)d_in[1];
    const int* depth_ptr = (n_in > 2) ? (const int*)d_in[2] : nullptr;
    float* out = (float*)d_out;

    const int dyn_smem = ROWS * DIM * 4 + NSTAGE * STAGE_E * 16;  // 65536 + 98304
    cudaFuncSetAttribute(rvq_kernel, cudaFuncAttributeMaxDynamicSharedMemorySize, dyn_smem);

    dim3 pg(KS / 32, (DIM / 4) / 32);
    dim3 pb(32, 8);
    pack_codebook_kernel<<<pg, pb>>>(cb);

    rvq_kernel<<<N_ROWS / ROWS, THREADS, dyn_smem>>>(x, cb, depth_ptr, out);
}

// round 3
// speedup vs baseline: 2.7351x; 1.1489x over previous
#include <cuda_runtime.h>
#include <cstdint>
#include <cstddef>

// Residual VQ, round 3: wider register tile for ILP.
// R2 was latency-bound (fma=45%, L1=46%, issue=39%, occ=12.5%): 32 accs and
// 12 LDS / 64 FFMA2 could not hide latency at 2 warps/SMSP.
// R3: per-thread 16 rows x 4 codes = 64 independent FFMA2 accumulators,
// BN=512 codes per sweep block -> 32 LDS-wavefronts per 128 FFMA2 (0.5 ratio).
// FMA floor measured from R2 calibration: ~3.8 ms @ 2 FFMA2-warp-inst/cyc/SM.

#define DIM      512
#define KS       4096
#define N_ROWS   16384
#define ROWS     32            // rows per CTA
#define THREADS  256
#define TM       16            // rows per thread
#define TN       4             // codes per thread (strided by 32 lanes)
#define BN       512           // codes per CTA sweep block (4 groups of 128)
#define BK       16            // k per stage
#define NSTAGE   3
#define QPS      (BK / 4)      // k-quads per stage = 4
#define NBLOCKS  (KS / BN)     // 8
#define KSTAGES  (DIM / BK)    // 32
#define TOTSTAGES (NBLOCKS * KSTAGES)  // 256 per depth
#define STAGE_E  (QPS * BN)    // 2048 float4 per stage (32KB)

// Packed codebook: g_cbq[q * KS + c] = float4(cb[c][4q..4q+3]).
// Layout [DIM/4][KS] so a stage tile row (fixed q, BN codes) is contiguous.
__device__ float4 g_cbq[(size_t)(DIM / 4) * KS];

// ---------------------------------------------------------------------------
// Pack kernel: transpose codebook into k-quad-major float4 layout.
// grid (KS/32, (DIM/4)/32) = (128, 4), block (32, 8).
// ---------------------------------------------------------------------------
__global__ void pack_codebook_kernel(const float* __restrict__ cb) {
    __shared__ float4 tile[32][33];
    const int c0 = blockIdx.x * 32;
    const int q0 = blockIdx.y * 32;
    const int tx = threadIdx.x;
    const int ty = threadIdx.y;
    const float4* cb4 = reinterpret_cast<const float4*>(cb);
#pragma unroll
    for (int i = 0; i < 4; i++) {
        const int c = c0 + ty + 8 * i;
        tile[ty + 8 * i][tx] = cb4[(size_t)c * (DIM / 4) + q0 + tx];
    }
    __syncthreads();
#pragma unroll
    for (int i = 0; i < 4; i++) {
        const int q = q0 + ty + 8 * i;
        g_cbq[(size_t)q * KS + c0 + tx] = tile[tx][ty + 8 * i];
    }
}

// ---------------------------------------------------------------------------
// Packed fp32x2 helpers (Blackwell sm_100+)
// ---------------------------------------------------------------------------
__device__ __forceinline__ unsigned long long ffma2(unsigned long long a,
                                                    unsigned long long b,
                                                    unsigned long long c) {
    unsigned long long d;
    asm("fma.rn.f32x2 %0, %1, %2, %3;" : "=l"(d) : "l"(a), "l"(b), "l"(c));
    return d;
}

__device__ __forceinline__ float lo_plus_hi(unsigned long long v) {
    float x, y;
    asm("mov.b64 {%0, %1}, %2;" : "=f"(x), "=f"(y) : "l"(v));
    return x + y;
}

__device__ __forceinline__ void cp_async16(void* smem_dst, const void* gmem_src) {
    unsigned s = (unsigned)__cvta_generic_to_shared(smem_dst);
    asm volatile("cp.async.cg.shared.global [%0], [%1], 16;" :: "r"(s), "l"(gmem_src));
}
__device__ __forceinline__ void cp_commit() { asm volatile("cp.async.commit_group;"); }
__device__ __forceinline__ void cp_wait1()  { asm volatile("cp.async.wait_group 1;"); }
__device__ __forceinline__ void cp_wait0()  { asm volatile("cp.async.wait_group 0;"); }

// ---------------------------------------------------------------------------
// Main fused RVQ kernel. grid = 512, block = 256.
// Dynamic smem: 64KB residual + 3*32KB cb stages = 160KB -> 1 CTA/SM.
// ---------------------------------------------------------------------------
__global__ void __launch_bounds__(THREADS, 1)
rvq_kernel(const float* __restrict__ x, const float* __restrict__ cb,
           const int* __restrict__ depth_ptr, float* __restrict__ out) {
    extern __shared__ __align__(16) unsigned char dynsmem[];
    float*  s_r  = reinterpret_cast<float*>(dynsmem);                    // [32][512]
    float4* s_cb = reinterpret_cast<float4*>(dynsmem + ROWS * DIM * 4);  // 3 stages

    __shared__ float s_bv[8][TM];
    __shared__ int   s_bi[8][TM];
    __shared__ float s_u[ROWS];
    __shared__ int   s_arg[ROWS];

    const int tid    = threadIdx.x;
    const int warp   = tid >> 5;
    const int lane   = tid & 31;
    const int rgroup = warp & 1;   // rows rgroup*16 .. +15
    const int cgroup = warp >> 1;  // codes cgroup*128 .. +127 within BN block
    const size_t row0 = (size_t)blockIdx.x * ROWS;

    int depth = 4;
    if (depth_ptr) {
        const int d = *depth_ptr;
        if (d >= 0 && d <= 32) depth = d;
    }

    // Load residual = x rows (coalesced float4).
    const float4* x4 = reinterpret_cast<const float4*>(x + row0 * DIM);
    float4* s4 = reinterpret_cast<float4*>(s_r);
    for (int i = tid; i < ROWS * DIM / 4; i += THREADS) s4[i] = x4[i];
    __syncthreads();

    // Stage s covers k-quads kq0..kq0+3 (kq0 = (s&31)*QPS) and codes c0..c0+511.
    auto copy_stage = [&](int s) {
        const int kq0 = (s & (KSTAGES - 1)) * QPS;
        const int c0  = (s / KSTAGES) * BN;
        float4* dst = s_cb + (s % NSTAGE) * STAGE_E;
        const float4* src = g_cbq + (size_t)kq0 * KS + c0;
#pragma unroll
        for (int j = 0; j < 8; j++) {
            const int e = tid + THREADS * j;   // e = q*BN + c
            const int q = e >> 9;
            const int c = e & (BN - 1);
            cp_async16(dst + e, src + (size_t)q * KS + c);
        }
    };

    for (int d = 0; d < depth; d++) {
        unsigned long long acc[TM][TN];
#pragma unroll
        for (int i = 0; i < TM; i++)
#pragma unroll
            for (int j = 0; j < TN; j++) acc[i][j] = 0ull;

        float rb_v[TM];
        int   rb_i[TM];
#pragma unroll
        for (int i = 0; i < TM; i++) { rb_v[i] = -3.0e38f; rb_i[i] = 0x7fffffff; }

        copy_stage(0); cp_commit();
        copy_stage(1); cp_commit();

        for (int s = 0; s < TOTSTAGES; s++) {
            cp_wait1();          // stage s resident
            __syncthreads();     // all warps finished compute(s-1); its buffer reusable
            if (s + 2 < TOTSTAGES) copy_stage(s + 2);
            cp_commit();

            // ---- compute stage s: QPS k-quads, 128 FFMA2 per quad per thread ----
            const float4* cbs = s_cb + (s % NSTAGE) * STAGE_E + cgroup * 128 + lane;
            const float*  ar  = s_r + (rgroup * TM) * DIM + (s & (KSTAGES - 1)) * BK;
#pragma unroll
            for (int q = 0; q < QPS; q++) {
                const ulonglong2 b0 = *reinterpret_cast<const ulonglong2*>(cbs + (size_t)q * BN + 0);
                const ulonglong2 b1 = *reinterpret_cast<const ulonglong2*>(cbs + (size_t)q * BN + 32);
                const ulonglong2 b2 = *reinterpret_cast<const ulonglong2*>(cbs + (size_t)q * BN + 64);
                const ulonglong2 b3 = *reinterpret_cast<const ulonglong2*>(cbs + (size_t)q * BN + 96);
#pragma unroll
                for (int i = 0; i < TM; i++) {
                    const ulonglong2 a = *reinterpret_cast<const ulonglong2*>(ar + i * DIM + q * 4);
                    acc[i][0] = ffma2(a.x, b0.x, acc[i][0]);
                    acc[i][0] = ffma2(a.y, b0.y, acc[i][0]);
                    acc[i][1] = ffma2(a.x, b1.x, acc[i][1]);
                    acc[i][1] = ffma2(a.y, b1.y, acc[i][1]);
                    acc[i][2] = ffma2(a.x, b2.x, acc[i][2]);
                    acc[i][2] = ffma2(a.y, b2.y, acc[i][2]);
                    acc[i][3] = ffma2(a.x, b3.x, acc[i][3]);
                    acc[i][3] = ffma2(a.y, b3.y, acc[i][3]);
                }
            }

            // ---- block epilogue: full k swept for this 512-code block ----
            if ((s & (KSTAGES - 1)) == (KSTAGES - 1)) {
                const int cbase = (s / KSTAGES) * BN + cgroup * 128 + lane;
#pragma unroll
                for (int i = 0; i < TM; i++) {
                    float v  = lo_plus_hi(acc[i][0]);
                    int  idx = cbase;
#pragma unroll
                    for (int j = 1; j < TN; j++) {
                        const float fv = lo_plus_hi(acc[i][j]);
                        if (fv > v) { v = fv; idx = cbase + 32 * j; }  // ascending idx: strict >
                    }
#pragma unroll
                    for (int off = 16; off > 0; off >>= 1) {
                        const float ov = __shfl_xor_sync(0xffffffffu, v, off);
                        const int   oi = __shfl_xor_sync(0xffffffffu, idx, off);
                        if (ov > v || (ov == v && oi < idx)) { v = ov; idx = oi; }
                    }
                    if (v > rb_v[i] || (v == rb_v[i] && idx < rb_i[i])) {
                        rb_v[i] = v; rb_i[i] = idx;
                    }
#pragma unroll
                    for (int j = 0; j < TN; j++) acc[i][j] = 0ull;
                }
            }
        }
        cp_wait0();

        // ---- depth end: merge 4 code-group warps per row-group ----
        if (lane == 0) {
#pragma unroll
            for (int i = 0; i < TM; i++) { s_bv[warp][i] = rb_v[i]; s_bi[warp][i] = rb_i[i]; }
        }
        __syncthreads();
        if (tid < ROWS) {
            const int r = tid;
            const int w0 = r >> 4;        // base warp owning this row-group
            const int ri = r & (TM - 1);
            float v  = s_bv[w0][ri];
            int  idx = s_bi[w0][ri];
#pragma unroll
            for (int w = 1; w < 4; w++) {
                const float ov = s_bv[w0 + 2 * w][ri];
                const int   oi = s_bi[w0 + 2 * w][ri];
                if (ov > v || (ov == v && oi < idx)) { v = ov; idx = oi; }
            }
            s_u[r] = v; s_arg[r] = idx;
        }
        __syncthreads();

        // residual[r] -= u[r] * cb[arg[r]]; warp w handles rows w, w+8, w+16, w+24
#pragma unroll
        for (int rr = 0; rr < 4; rr++) {
            const int r = warp + rr * 8;
            const float u = s_u[r];
            const float4* crow = reinterpret_cast<const float4*>(cb + (size_t)s_arg[r] * DIM);
            float4* rrow = reinterpret_cast<float4*>(s_r + r * DIM);
#pragma unroll
            for (int t = 0; t < 4; t++) {
                const int k4 = lane + 32 * t;
                const float4 c4 = crow[k4];
                float4 v4 = rrow[k4];
                v4.x -= u * c4.x; v4.y -= u * c4.y; v4.z -= u * c4.z; v4.w -= u * c4.w;
                rrow[k4] = v4;
            }
        }
        __syncthreads();
    }

    // total = x - residual_final
    float4* o4 = reinterpret_cast<float4*>(out + row0 * DIM);
    for (int i = tid; i < ROWS * DIM / 4; i += THREADS) {
        const float4 xv = x4[i];
        const float4 rv = s4[i];
        o4[i] = make_float4(xv.x - rv.x, xv.y - rv.y, xv.z - rv.z, xv.w - rv.w);
    }
}

// ---------------------------------------------------------------------------
extern "C" void kernel_launch(void* const* d_in, const int* in_sizes, int n_in,
                              void* d_out, int out_size) {
    const float* x  = (const float*)d_in[0];
    const float* cb = (const float*)d_in[1];
    const int* depth_ptr = (n_in > 2) ? (const int*)d_in[2] : nullptr;
    float* out = (float*)d_out;

    const int dyn_smem = ROWS * DIM * 4 + NSTAGE * STAGE_E * 16;  // 65536 + 98304
    cudaFuncSetAttribute(rvq_kernel, cudaFuncAttributeMaxDynamicSharedMemorySize, dyn_smem);

    dim3 pg(KS / 32, (DIM / 4) / 32);
    dim3 pb(32, 8);
    pack_codebook_kernel<<<pg, pb>>>(cb);

    rvq_kernel<<<N_ROWS / ROWS, THREADS, dyn_smem>>>(x, cb, depth_ptr, out);
}

// round 4
// speedup vs baseline: 2.7366x; 1.0005x over previous
#include <cuda_runtime.h>
#include <cstdint>
#include <cstddef>

// Residual VQ, round 3: wider register tile for ILP.
// R2 was latency-bound (fma=45%, L1=46%, issue=39%, occ=12.5%): 32 accs and
// 12 LDS / 64 FFMA2 could not hide latency at 2 warps/SMSP.
// R3: per-thread 16 rows x 4 codes = 64 independent FFMA2 accumulators,
// BN=512 codes per sweep block -> 32 LDS-wavefronts per 128 FFMA2 (0.5 ratio).
// FMA floor measured from R2 calibration: ~3.8 ms @ 2 FFMA2-warp-inst/cyc/SM.

#define DIM      512
#define KS       4096
#define N_ROWS   16384
#define ROWS     32            // rows per CTA
#define THREADS  256
#define TM       16            // rows per thread
#define TN       4             // codes per thread (strided by 32 lanes)
#define BN       512           // codes per CTA sweep block (4 groups of 128)
#define BK       16            // k per stage
#define NSTAGE   3
#define QPS      (BK / 4)      // k-quads per stage = 4
#define NBLOCKS  (KS / BN)     // 8
#define KSTAGES  (DIM / BK)    // 32
#define TOTSTAGES (NBLOCKS * KSTAGES)  // 256 per depth
#define STAGE_E  (QPS * BN)    // 2048 float4 per stage (32KB)

// Packed codebook: g_cbq[q * KS + c] = float4(cb[c][4q..4q+3]).
// Layout [DIM/4][KS] so a stage tile row (fixed q, BN codes) is contiguous.
__device__ float4 g_cbq[(size_t)(DIM / 4) * KS];

// ---------------------------------------------------------------------------
// Pack kernel: transpose codebook into k-quad-major float4 layout.
// grid (KS/32, (DIM/4)/32) = (128, 4), block (32, 8).
// ---------------------------------------------------------------------------
__global__ void pack_codebook_kernel(const float* __restrict__ cb) {
    __shared__ float4 tile[32][33];
    const int c0 = blockIdx.x * 32;
    const int q0 = blockIdx.y * 32;
    const int tx = threadIdx.x;
    const int ty = threadIdx.y;
    const float4* cb4 = reinterpret_cast<const float4*>(cb);
#pragma unroll
    for (int i = 0; i < 4; i++) {
        const int c = c0 + ty + 8 * i;
        tile[ty + 8 * i][tx] = cb4[(size_t)c * (DIM / 4) + q0 + tx];
    }
    __syncthreads();
#pragma unroll
    for (int i = 0; i < 4; i++) {
        const int q = q0 + ty + 8 * i;
        g_cbq[(size_t)q * KS + c0 + tx] = tile[tx][ty + 8 * i];
    }
}

// ---------------------------------------------------------------------------
// Packed fp32x2 helpers (Blackwell sm_100+)
// ---------------------------------------------------------------------------
__device__ __forceinline__ unsigned long long ffma2(unsigned long long a,
                                                    unsigned long long b,
                                                    unsigned long long c) {
    unsigned long long d;
    asm("fma.rn.f32x2 %0, %1, %2, %3;" : "=l"(d) : "l"(a), "l"(b), "l"(c));
    return d;
}

__device__ __forceinline__ float lo_plus_hi(unsigned long long v) {
    float x, y;
    asm("mov.b64 {%0, %1}, %2;" : "=f"(x), "=f"(y) : "l"(v));
    return x + y;
}

__device__ __forceinline__ void cp_async16(void* smem_dst, const void* gmem_src) {
    unsigned s = (unsigned)__cvta_generic_to_shared(smem_dst);
    asm volatile("cp.async.cg.shared.global [%0], [%1], 16;" :: "r"(s), "l"(gmem_src));
}
__device__ __forceinline__ void cp_commit() { asm volatile("cp.async.commit_group;"); }
__device__ __forceinline__ void cp_wait1()  { asm volatile("cp.async.wait_group 1;"); }
__device__ __forceinline__ void cp_wait0()  { asm volatile("cp.async.wait_group 0;"); }

// ---------------------------------------------------------------------------
// Main fused RVQ kernel. grid = 512, block = 256.
// Dynamic smem: 64KB residual + 3*32KB cb stages = 160KB -> 1 CTA/SM.
// ---------------------------------------------------------------------------
__global__ void __launch_bounds__(THREADS, 1)
rvq_kernel(const float* __restrict__ x, const float* __restrict__ cb,
           const int* __restrict__ depth_ptr, float* __restrict__ out) {
    extern __shared__ __align__(16) unsigned char dynsmem[];
    float*  s_r  = reinterpret_cast<float*>(dynsmem);                    // [32][512]
    float4* s_cb = reinterpret_cast<float4*>(dynsmem + ROWS * DIM * 4);  // 3 stages

    __shared__ float s_bv[8][TM];
    __shared__ int   s_bi[8][TM];
    __shared__ float s_u[ROWS];
    __shared__ int   s_arg[ROWS];

    const int tid    = threadIdx.x;
    const int warp   = tid >> 5;
    const int lane   = tid & 31;
    const int rgroup = warp & 1;   // rows rgroup*16 .. +15
    const int cgroup = warp >> 1;  // codes cgroup*128 .. +127 within BN block
    const size_t row0 = (size_t)blockIdx.x * ROWS;

    int depth = 4;
    if (depth_ptr) {
        const int d = *depth_ptr;
        if (d >= 0 && d <= 32) depth = d;
    }

    // Load residual = x rows (coalesced float4).
    const float4* x4 = reinterpret_cast<const float4*>(x + row0 * DIM);
    float4* s4 = reinterpret_cast<float4*>(s_r);
    for (int i = tid; i < ROWS * DIM / 4; i += THREADS) s4[i] = x4[i];
    __syncthreads();

    // Stage s covers k-quads kq0..kq0+3 (kq0 = (s&31)*QPS) and codes c0..c0+511.
    auto copy_stage = [&](int s) {
        const int kq0 = (s & (KSTAGES - 1)) * QPS;
        const int c0  = (s / KSTAGES) * BN;
        float4* dst = s_cb + (s % NSTAGE) * STAGE_E;
        const float4* src = g_cbq + (size_t)kq0 * KS + c0;
#pragma unroll
        for (int j = 0; j < 8; j++) {
            const int e = tid + THREADS * j;   // e = q*BN + c
            const int q = e >> 9;
            const int c = e & (BN - 1);
            cp_async16(dst + e, src + (size_t)q * KS + c);
        }
    };

    for (int d = 0; d < depth; d++) {
        unsigned long long acc[TM][TN];
#pragma unroll
        for (int i = 0; i < TM; i++)
#pragma unroll
            for (int j = 0; j < TN; j++) acc[i][j] = 0ull;

        float rb_v[TM];
        int   rb_i[TM];
#pragma unroll
        for (int i = 0; i < TM; i++) { rb_v[i] = -3.0e38f; rb_i[i] = 0x7fffffff; }

        copy_stage(0); cp_commit();
        copy_stage(1); cp_commit();

        for (int s = 0; s < TOTSTAGES; s++) {
            cp_wait1();          // stage s resident
            __syncthreads();     // all warps finished compute(s-1); its buffer reusable
            if (s + 2 < TOTSTAGES) copy_stage(s + 2);
            cp_commit();

            // ---- compute stage s: QPS k-quads, 128 FFMA2 per quad per thread ----
            const float4* cbs = s_cb + (s % NSTAGE) * STAGE_E + cgroup * 128 + lane;
            const float*  ar  = s_r + (rgroup * TM) * DIM + (s & (KSTAGES - 1)) * BK;
#pragma unroll
            for (int q = 0; q < QPS; q++) {
                const ulonglong2 b0 = *reinterpret_cast<const ulonglong2*>(cbs + (size_t)q * BN + 0);
                const ulonglong2 b1 = *reinterpret_cast<const ulonglong2*>(cbs + (size_t)q * BN + 32);
                const ulonglong2 b2 = *reinterpret_cast<const ulonglong2*>(cbs + (size_t)q * BN + 64);
                const ulonglong2 b3 = *reinterpret_cast<const ulonglong2*>(cbs + (size_t)q * BN + 96);
#pragma unroll
                for (int i = 0; i < TM; i++) {
                    const ulonglong2 a = *reinterpret_cast<const ulonglong2*>(ar + i * DIM + q * 4);
                    acc[i][0] = ffma2(a.x, b0.x, acc[i][0]);
                    acc[i][0] = ffma2(a.y, b0.y, acc[i][0]);
                    acc[i][1] = ffma2(a.x, b1.x, acc[i][1]);
                    acc[i][1] = ffma2(a.y, b1.y, acc[i][1]);
                    acc[i][2] = ffma2(a.x, b2.x, acc[i][2]);
                    acc[i][2] = ffma2(a.y, b2.y, acc[i][2]);
                    acc[i][3] = ffma2(a.x, b3.x, acc[i][3]);
                    acc[i][3] = ffma2(a.y, b3.y, acc[i][3]);
                }
            }

            // ---- block epilogue: full k swept for this 512-code block ----
            if ((s & (KSTAGES - 1)) == (KSTAGES - 1)) {
                const int cbase = (s / KSTAGES) * BN + cgroup * 128 + lane;
#pragma unroll
                for (int i = 0; i < TM; i++) {
                    float v  = lo_plus_hi(acc[i][0]);
                    int  idx = cbase;
#pragma unroll
                    for (int j = 1; j < TN; j++) {
                        const float fv = lo_plus_hi(acc[i][j]);
                        if (fv > v) { v = fv; idx = cbase + 32 * j; }  // ascending idx: strict >
                    }
#pragma unroll
                    for (int off = 16; off > 0; off >>= 1) {
                        const float ov = __shfl_xor_sync(0xffffffffu, v, off);
                        const int   oi = __shfl_xor_sync(0xffffffffu, idx, off);
                        if (ov > v || (ov == v && oi < idx)) { v = ov; idx = oi; }
                    }
                    if (v > rb_v[i] || (v == rb_v[i] && idx < rb_i[i])) {
                        rb_v[i] = v; rb_i[i] = idx;
                    }
#pragma unroll
                    for (int j = 0; j < TN; j++) acc[i][j] = 0ull;
                }
            }
        }
        cp_wait0();

        // ---- depth end: merge 4 code-group warps per row-group ----
        if (lane == 0) {
#pragma unroll
            for (int i = 0; i < TM; i++) { s_bv[warp][i] = rb_v[i]; s_bi[warp][i] = rb_i[i]; }
        }
        __syncthreads();
        if (tid < ROWS) {
            const int r = tid;
            const int w0 = r >> 4;        // base warp owning this row-group
            const int ri = r & (TM - 1);
            float v  = s_bv[w0][ri];
            int  idx = s_bi[w0][ri];
#pragma unroll
            for (int w = 1; w < 4; w++) {
                const float ov = s_bv[w0 + 2 * w][ri];
                const int   oi = s_bi[w0 + 2 * w][ri];
                if (ov > v || (ov == v && oi < idx)) { v = ov; idx = oi; }
            }
            s_u[r] = v; s_arg[r] = idx;
        }
        __syncthreads();

        // residual[r] -= u[r] * cb[arg[r]]; warp w handles rows w, w+8, w+16, w+24
#pragma unroll
        for (int rr = 0; rr < 4; rr++) {
            const int r = warp + rr * 8;
            const float u = s_u[r];
            const float4* crow = reinterpret_cast<const float4*>(cb + (size_t)s_arg[r] * DIM);
            float4* rrow = reinterpret_cast<float4*>(s_r + r * DIM);
#pragma unroll
            for (int t = 0; t < 4; t++) {
                const int k4 = lane + 32 * t;
                const float4 c4 = crow[k4];
                float4 v4 = rrow[k4];
                v4.x -= u * c4.x; v4.y -= u * c4.y; v4.z -= u * c4.z; v4.w -= u * c4.w;
                rrow[k4] = v4;
            }
        }
        __syncthreads();
    }

    // total = x - residual_final
    float4* o4 = reinterpret_cast<float4*>(out + row0 * DIM);
    for (int i = tid; i < ROWS * DIM / 4; i += THREADS) {
        const float4 xv = x4[i];
        const float4 rv = s4[i];
        o4[i] = make_float4(xv.x - rv.x, xv.y - rv.y, xv.z - rv.z, xv.w - rv.w);
    }
}

// ---------------------------------------------------------------------------
extern "C" void kernel_launch(void* const* d_in, const int* in_sizes, int n_in,
                              void* d_out, int out_size) {
    const float* x  = (const float*)d_in[0];
    const float* cb = (const float*)d_in[1];
    const int* depth_ptr = (n_in > 2) ? (const int*)d_in[2] : nullptr;
    float* out = (float*)d_out;

    const int dyn_smem = ROWS * DIM * 4 + NSTAGE * STAGE_E * 16;  // 65536 + 98304
    cudaFuncSetAttribute(rvq_kernel, cudaFuncAttributeMaxDynamicSharedMemorySize, dyn_smem);

    dim3 pg(KS / 32, (DIM / 4) / 32);
    dim3 pb(32, 8);
    pack_codebook_kernel<<<pg, pb>>>(cb);

    rvq_kernel<<<N_ROWS / ROWS, THREADS, dyn_smem>>>(x, cb, depth_ptr, out);
}

// round 6
// speedup vs baseline: 12.7037x; 4.6422x over previous
#include <cuda_runtime.h>
#include <cuda_bf16.h>
#include <cstdint>
#include <cstddef>

// Residual VQ, round 6: Ampere-style warp MMA (bf16 HMMA fallback on Blackwell;
// tcgen05 is unavailable because the harness compiles PTX for compute_100 base).
//
// ip ~= bf16(residual) @ bf16(cb)^T per depth via mma.sync.m16n8k16 (fp32 acc).
// Per row: top-2 per owning thread (16 candidates) -> exact fp32 rescore ->
// argmax (tie: lowest index) -> fp32 residual update. total = x - residual.

#define NTOK     16384
#define DIM      512
#define KS       4096
#define MC       128            // rows per CTA -> grid 128
#define THREADS  256
#define NWARP    8
#define BN       64             // codes per B tile
#define NTILES   (KS / BN)      // 64
#define BK       128            // k per B tile chunk
#define NCHUNK   (DIM / BK)     // 4
#define UNITS    (NTILES * NCHUNK)  // 256
#define BTILE_BYTES (BN * BK * 2)   // 16384
#define NBUF     4
#define A_BYTES  (MC * DIM * 2)     // 131072

__device__ float         g_res[(size_t)NTOK * DIM];   // fp32 residual master
__device__ __nv_bfloat16 g_cbh[(size_t)KS * DIM];     // bf16 codebook

// ---------------------------------------------------------------------------
// helpers
// ---------------------------------------------------------------------------
static __device__ __forceinline__ uint32_t smem_u32(const void* p) {
    return (uint32_t)__cvta_generic_to_shared(p);
}
static __device__ __forceinline__ void ldsm4(uint32_t* r, uint32_t a) {
    asm volatile("ldmatrix.sync.aligned.m8n8.x4.shared.b16 {%0,%1,%2,%3}, [%4];"
                 : "=r"(r[0]), "=r"(r[1]), "=r"(r[2]), "=r"(r[3]) : "r"(a));
}
static __device__ __forceinline__ void mma16816(float* c, const uint32_t* a,
                                                const uint32_t* b) {
    asm volatile("mma.sync.aligned.m16n8k16.row.col.f32.bf16.bf16.f32 "
                 "{%0,%1,%2,%3}, {%4,%5,%6,%7}, {%8,%9}, {%0,%1,%2,%3};"
                 : "+f"(c[0]), "+f"(c[1]), "+f"(c[2]), "+f"(c[3])
                 : "r"(a[0]), "r"(a[1]), "r"(a[2]), "r"(a[3]),
                   "r"(b[0]), "r"(b[1]));
}
static __device__ __forceinline__ void cp16(uint32_t dst, const void* src) {
    asm volatile("cp.async.cg.shared.global [%0], [%1], 16;" :: "r"(dst), "l"(src));
}
static __device__ __forceinline__ void cp_commit() { asm volatile("cp.async.commit_group;"); }
static __device__ __forceinline__ void cp_wait2()  { asm volatile("cp.async.wait_group 2;"); }
static __device__ __forceinline__ void cp_wait0()  { asm volatile("cp.async.wait_group 0;"); }

static __device__ __forceinline__ uint32_t pack_bf2(float a, float b) {
    __nv_bfloat162 h = __floats2bfloat162_rn(a, b);
    return *reinterpret_cast<uint32_t*>(&h);
}

// ---------------------------------------------------------------------------
// pack codebook to bf16. grid 2048 x 256 threads, 4 elems each.
// ---------------------------------------------------------------------------
__global__ void pack_cb_kernel(const float* __restrict__ cb) {
    const size_t i = ((size_t)blockIdx.x * 256 + threadIdx.x) * 4;
    const float4 v = *reinterpret_cast<const float4*>(cb + i);
    uint2 o;
    o.x = pack_bf2(v.x, v.y);
    o.y = pack_bf2(v.z, v.w);
    *reinterpret_cast<uint2*>(&g_cbh[i]) = o;
}

// ---------------------------------------------------------------------------
// main kernel: grid 128 CTAs x 256 threads.
// dyn smem: A 128KB (bf16 residual, SW-swizzled) + 4 x 16KB B ring = 192KB.
// ---------------------------------------------------------------------------
__global__ void __launch_bounds__(THREADS, 1)
rvq_mma_kernel(const float* __restrict__ x, const float* __restrict__ cb,
               const int* __restrict__ depth_ptr, float* __restrict__ out) {
    extern __shared__ __align__(1024) unsigned char raw[];
    unsigned char* sAp = raw;                        // [128 rows][512 bf16] swizzled
    const uint32_t sA  = smem_u32(sAp);
    const uint32_t sB0 = smem_u32(raw + A_BYTES);    // 4 ring buffers

    __shared__ float s_cv[MC][16];
    __shared__ int   s_ci[MC][16];
    __shared__ float s_u[MC];
    __shared__ int   s_code[MC];

    const int tid  = threadIdx.x;
    const int warp = tid >> 5;
    const int lane = tid & 31;
    const int wm   = warp >> 1;     // row group: rows wm*32 .. +31
    const int wn   = warp & 1;      // code half within B tile: wn*32 .. +31
    const size_t row0 = (size_t)blockIdx.x * MC;

    int depth = 4;
    if (depth_ptr) {
        const int dd = *depth_ptr;
        if (dd >= 0 && dd <= 8) depth = dd;
    }

    // ---- init: residual = x (fp32 global) + bf16 A tile in smem ----
    for (int e = tid; e < MC * 64; e += THREADS) {
        const int row = e >> 6, c = e & 63;      // c = 16B chunk (8 floats)
        const float4* src = reinterpret_cast<const float4*>(x + (row0 + row) * DIM + c * 8);
        const float4 v0 = src[0], v1 = src[1];
        float4* dres = reinterpret_cast<float4*>(g_res + (row0 + row) * DIM + c * 8);
        dres[0] = v0; dres[1] = v1;
        uint4 pk;
        pk.x = pack_bf2(v0.x, v0.y); pk.y = pack_bf2(v0.z, v0.w);
        pk.z = pack_bf2(v1.x, v1.y); pk.w = pack_bf2(v1.z, v1.w);
        *reinterpret_cast<uint4*>(sAp + row * 1024 + ((c ^ (row & 7)) << 4)) = pk;
    }
    __syncthreads();

    // B tile fill: 1024 x 16B chunks, 4 per thread, SW-swizzled 256B rows.
    auto fillB = [&](int u) {
        const int nt = u >> 2, kc = u & 3;
        const uint32_t dst = sB0 + (uint32_t)(u & (NBUF - 1)) * BTILE_BYTES;
        const __nv_bfloat16* src = g_cbh + (size_t)(nt * BN) * DIM + kc * BK;
#pragma unroll
        for (int i = 0; i < 4; i++) {
            const int e = tid + THREADS * i;
            const int rowb = e >> 4, c = e & 15;
            cp16(dst + rowb * 256 + ((c ^ (rowb & 7)) << 4),
                 src + (size_t)rowb * DIM + c * 8);
        }
    };

    // per-thread fragment address constants
    const int lm = lane & 15, lh = lane >> 4;
    const int arow = wm * 32 + lm;
    const int axor = arow & 7;
    const uint32_t cA0 = sA + (uint32_t)arow * 1024;
    const uint32_t cA1 = cA0 + 16u * 1024u;
    const int grp = lane >> 3, lrow = lane & 7, kpar = grp & 1;
    const int rowoff = ((grp >> 1) << 3) + lrow;

    for (int d = 0; d < depth; d++) {
        float acc[2][4][4];
#pragma unroll
        for (int mi = 0; mi < 2; mi++)
#pragma unroll
            for (int ni = 0; ni < 4; ni++)
#pragma unroll
                for (int j = 0; j < 4; j++) acc[mi][ni][j] = 0.0f;

        // per-thread running top-2 for its 4 owned rows
        float t1v[4], t2v[4]; int t1i[4], t2i[4];
#pragma unroll
        for (int r = 0; r < 4; r++) {
            t1v[r] = -3.0e38f; t2v[r] = -3.0e38f;
            t1i[r] = 0x7fffffff; t2i[r] = 0x7fffffff;
        }

        fillB(0); cp_commit();
        fillB(1); cp_commit();
        fillB(2); cp_commit();

        for (int u = 0; u < UNITS; u++) {
            const int nt = u >> 2, kc = u & 3;

            cp_wait2();           // fill(u) complete for this thread
            __syncthreads();      // ... and for all threads; compute(u-1) done
            if (u + 3 < UNITS) fillB(u + 3);
            cp_commit();

            const uint32_t sB  = sB0 + (uint32_t)(u & (NBUF - 1)) * BTILE_BYTES;
            const uint32_t cB0 = sB + (uint32_t)(wn * 32 + rowoff) * 256;
            const uint32_t cB1 = cB0 + 16u * 256u;

#pragma unroll
            for (int ks = 0; ks < 8; ks++) {
                uint32_t a0[4], a1[4], b01[4], b23[4];
                const int ck = kc * 16 + ks * 2 + lh;       // A k-chunk in row
                const uint32_t aoff = (uint32_t)((ck ^ axor) << 4);
                ldsm4(a0, cA0 + aoff);
                ldsm4(a1, cA1 + aoff);
                const uint32_t boff = (uint32_t)((((ks * 2 + kpar)) ^ lrow) << 4);
                ldsm4(b01, cB0 + boff);
                ldsm4(b23, cB1 + boff);
                mma16816(acc[0][0], a0, b01 + 0);
                mma16816(acc[0][1], a0, b01 + 2);
                mma16816(acc[0][2], a0, b23 + 0);
                mma16816(acc[0][3], a0, b23 + 2);
                mma16816(acc[1][0], a1, b01 + 0);
                mma16816(acc[1][1], a1, b01 + 2);
                mma16816(acc[1][2], a1, b23 + 0);
                mma16816(acc[1][3], a1, b23 + 2);
            }

            if (kc == NCHUNK - 1) {
                // ---- N-tile epilogue: update per-row top-2, reset accs ----
                const int cb0 = nt * BN + wn * 32 + 2 * (lane & 3);
#pragma unroll
                for (int mi = 0; mi < 2; mi++)
#pragma unroll
                    for (int rh = 0; rh < 2; rh++) {
                        const int ri = mi * 2 + rh;
#pragma unroll
                        for (int ni = 0; ni < 4; ni++)
#pragma unroll
                            for (int j = 0; j < 2; j++) {
                                const float v = acc[mi][ni][rh * 2 + j];
                                const int  ix = cb0 + ni * 8 + j;
                                if (v > t1v[ri]) {
                                    t2v[ri] = t1v[ri]; t2i[ri] = t1i[ri];
                                    t1v[ri] = v;       t1i[ri] = ix;
                                } else if (v > t2v[ri]) {
                                    t2v[ri] = v; t2i[ri] = ix;
                                }
                            }
#pragma unroll
                        for (int ni = 0; ni < 4; ni++) {
                            acc[mi][ni][rh * 2 + 0] = 0.0f;
                            acc[mi][ni][rh * 2 + 1] = 0.0f;
                        }
                    }
            }
        }
        cp_wait0();

        // ---- stash 16 candidates per row ----
#pragma unroll
        for (int mi = 0; mi < 2; mi++)
#pragma unroll
            for (int rh = 0; rh < 2; rh++) {
                const int ri  = mi * 2 + rh;
                const int row = wm * 32 + mi * 16 + rh * 8 + (lane >> 2);
                const int sb  = wn * 8 + (lane & 3) * 2;
                s_cv[row][sb]     = t1v[ri]; s_ci[row][sb]     = t1i[ri];
                s_cv[row][sb + 1] = t2v[ri]; s_ci[row][sb + 1] = t2i[ri];
            }
        __syncthreads();

        // ---- exact fp32 rescore of all 2048 (row, cand) pairs ----
        for (int i = 0; i < (MC * 16) / NWARP; i++) {   // 256 per warp
            const int p    = warp * ((MC * 16) / NWARP) + i;
            const int row  = p >> 4, slot = p & 15;
            const int cand = s_ci[row][slot];
            const float4* rr = reinterpret_cast<const float4*>(g_res + (row0 + row) * DIM);
            const float4* cc = reinterpret_cast<const float4*>(cb + (size_t)cand * DIM);
            float sum = 0.0f;
#pragma unroll
            for (int q = 0; q < 4; q++) {
                const float4 a = rr[lane + 32 * q];
                const float4 b = cc[lane + 32 * q];
                sum += a.x * b.x + a.y * b.y + a.z * b.z + a.w * b.w;
            }
#pragma unroll
            for (int off = 16; off; off >>= 1)
                sum += __shfl_xor_sync(0xffffffffu, sum, off);
            if (lane == 0) s_cv[row][slot] = sum;   // overwrite approx with exact
        }
        __syncthreads();

        // ---- winner per row (tie: lowest index) ----
        if (tid < MC) {
            float bv = s_cv[tid][0]; int bi = s_ci[tid][0];
#pragma unroll
            for (int t = 1; t < 16; t++) {
                const float v = s_cv[tid][t]; const int ix = s_ci[tid][t];
                if (v > bv || (v == bv && ix < bi)) { bv = v; bi = ix; }
            }
            s_u[tid] = bv; s_code[tid] = bi;
        }
        __syncthreads();

        // ---- residual update (fp32 global) + bf16 A refill (smem) ----
        for (int rr = 0; rr < MC / NWARP; rr++) {       // 16 rows per warp
            const int r = warp * (MC / NWARP) + rr;
            const float uv = s_u[r];
            const int code = s_code[r];
            float4* dres = reinterpret_cast<float4*>(g_res + (row0 + r) * DIM);
            const float4* cc = reinterpret_cast<const float4*>(cb + (size_t)code * DIM);
#pragma unroll
            for (int q = 0; q < 2; q++) {
                const int c = lane + 32 * q;            // 16B chunk index (8 floats)
                float4 v0 = dres[c * 2 + 0], v1 = dres[c * 2 + 1];
                const float4 c0 = cc[c * 2 + 0], c1 = cc[c * 2 + 1];
                v0.x -= uv * c0.x; v0.y -= uv * c0.y; v0.z -= uv * c0.z; v0.w -= uv * c0.w;
                v1.x -= uv * c1.x; v1.y -= uv * c1.y; v1.z -= uv * c1.z; v1.w -= uv * c1.w;
                dres[c * 2 + 0] = v0; dres[c * 2 + 1] = v1;
                uint4 pk;
                pk.x = pack_bf2(v0.x, v0.y); pk.y = pack_bf2(v0.z, v0.w);
                pk.z = pack_bf2(v1.x, v1.y); pk.w = pack_bf2(v1.z, v1.w);
                *reinterpret_cast<uint4*>(sAp + r * 1024 + ((c ^ (r & 7)) << 4)) = pk;
            }
        }
        __syncthreads();
    }

    // ---- output: total = x - residual_final ----
    const float4* x4 = reinterpret_cast<const float4*>(x + row0 * DIM);
    const float4* r4 = reinterpret_cast<const float4*>(g_res + row0 * DIM);
    float4* o4 = reinterpret_cast<float4*>(out + row0 * DIM);
    for (int i = tid; i < MC * DIM / 4; i += THREADS) {
        const float4 xv = x4[i];
        const float4 rv = r4[i];
        o4[i] = make_float4(xv.x - rv.x, xv.y - rv.y, xv.z - rv.z, xv.w - rv.w);
    }
}

// ---------------------------------------------------------------------------
extern "C" void kernel_launch(void* const* d_in, const int* in_sizes, int n_in,
                              void* d_out, int out_size) {
    const float* x  = (const float*)d_in[0];
    const float* cb = (const float*)d_in[1];
    const int* depth_ptr = (n_in > 2) ? (const int*)d_in[2] : nullptr;
    float* out = (float*)d_out;

    const int dyn_smem = A_BYTES + NBUF * BTILE_BYTES;   // 196608
    cudaFuncSetAttribute(rvq_mma_kernel, cudaFuncAttributeMaxDynamicSharedMemorySize,
                         dyn_smem);

    pack_cb_kernel<<<(KS * DIM / 4) / 256, 256>>>(cb);
    rvq_mma_kernel<<<NTOK / MC, THREADS, dyn_smem>>>(x, cb, depth_ptr, out);
}

// round 7
// speedup vs baseline: 16.8045x; 1.3228x over previous
#include <cuda_runtime.h>
#include <cuda_bf16.h>
#include <cstdint>
#include <cstddef>

// Residual VQ, round 7: 16-warp bf16 HMMA (m16n8k16), warp tile 32x32 over a
// 128x128 D tile (BN=128). 4 warps/SMSP hides MMA/LDSM latency (R6 had 2 and
// was latency-bound at tensor=31%). 2-buffer 32KB B ring halves barrier count.
// Top-2/thread (32 cands/row) -> approx top-8 prefilter -> exact fp32 rescore.

#define NTOK     16384
#define DIM      512
#define KS       4096
#define MC       128
#define THREADS  512
#define NWARP    16
#define BN       128
#define BK       128
#define NTILES   (KS / BN)          // 32
#define NCHUNK   (DIM / BK)         // 4
#define UNITS    (NTILES * NCHUNK)  // 128
#define BTILE_BYTES (BN * BK * 2)   // 32768
#define NBUF     2
#define A_BYTES  (MC * DIM * 2)     // 131072

__device__ float         g_res[(size_t)NTOK * DIM];   // fp32 residual master
__device__ __nv_bfloat16 g_cbh[(size_t)KS * DIM];     // bf16 codebook

// ---------------------------------------------------------------------------
static __device__ __forceinline__ uint32_t smem_u32(const void* p) {
    return (uint32_t)__cvta_generic_to_shared(p);
}
static __device__ __forceinline__ void ldsm4(uint32_t* r, uint32_t a) {
    asm volatile("ldmatrix.sync.aligned.m8n8.x4.shared.b16 {%0,%1,%2,%3}, [%4];"
                 : "=r"(r[0]), "=r"(r[1]), "=r"(r[2]), "=r"(r[3]) : "r"(a));
}
static __device__ __forceinline__ void mma16816(float* c, const uint32_t* a,
                                                const uint32_t* b) {
    asm volatile("mma.sync.aligned.m16n8k16.row.col.f32.bf16.bf16.f32 "
                 "{%0,%1,%2,%3}, {%4,%5,%6,%7}, {%8,%9}, {%0,%1,%2,%3};"
                 : "+f"(c[0]), "+f"(c[1]), "+f"(c[2]), "+f"(c[3])
                 : "r"(a[0]), "r"(a[1]), "r"(a[2]), "r"(a[3]),
                   "r"(b[0]), "r"(b[1]));
}
static __device__ __forceinline__ void cp16(uint32_t dst, const void* src) {
    asm volatile("cp.async.cg.shared.global [%0], [%1], 16;" :: "r"(dst), "l"(src));
}
static __device__ __forceinline__ void cp_commit() { asm volatile("cp.async.commit_group;"); }
static __device__ __forceinline__ void cp_wait0()  { asm volatile("cp.async.wait_group 0;"); }

static __device__ __forceinline__ uint32_t pack_bf2(float a, float b) {
    __nv_bfloat162 h = __floats2bfloat162_rn(a, b);
    return *reinterpret_cast<uint32_t*>(&h);
}

// ---------------------------------------------------------------------------
__global__ void pack_cb_kernel(const float* __restrict__ cb) {
    const size_t i = ((size_t)blockIdx.x * 256 + threadIdx.x) * 4;
    const float4 v = *reinterpret_cast<const float4*>(cb + i);
    uint2 o;
    o.x = pack_bf2(v.x, v.y);
    o.y = pack_bf2(v.z, v.w);
    *reinterpret_cast<uint2*>(&g_cbh[i]) = o;
}

// ---------------------------------------------------------------------------
// main: grid 128 CTAs x 512 threads.
// dyn smem: A 128KB (bf16 residual, swizzled) + 2 x 32KB B ring = 192KB.
// ---------------------------------------------------------------------------
__global__ void __launch_bounds__(THREADS, 1)
rvq_mma_kernel(const float* __restrict__ x, const float* __restrict__ cb,
               const int* __restrict__ depth_ptr, float* __restrict__ out) {
    extern __shared__ __align__(1024) unsigned char raw[];
    unsigned char* sAp = raw;                        // [128 rows][512 bf16] swizzled
    const uint32_t sA  = smem_u32(sAp);
    const uint32_t sB0 = smem_u32(raw + A_BYTES);    // 2 ring buffers

    __shared__ float s_cv[MC][32];
    __shared__ int   s_ci[MC][32];
    __shared__ float s_u[MC];
    __shared__ int   s_code[MC];

    const int tid  = threadIdx.x;
    const int warp = tid >> 5;
    const int lane = tid & 31;
    const int wm   = warp >> 2;     // row group: rows wm*32 .. +31
    const int wn   = warp & 3;      // code group within B tile: wn*32 .. +31
    const size_t row0 = (size_t)blockIdx.x * MC;

    int depth = 4;
    if (depth_ptr) {
        const int dd = *depth_ptr;
        if (dd >= 0 && dd <= 8) depth = dd;
    }

    // ---- init: residual = x (fp32 global) + bf16 A tile in smem ----
    for (int e = tid; e < MC * 64; e += THREADS) {
        const int row = e >> 6, c = e & 63;      // c = 16B chunk (8 floats)
        const float4* src = reinterpret_cast<const float4*>(x + (row0 + row) * DIM + c * 8);
        const float4 v0 = src[0], v1 = src[1];
        float4* dres = reinterpret_cast<float4*>(g_res + (row0 + row) * DIM + c * 8);
        dres[0] = v0; dres[1] = v1;
        uint4 pk;
        pk.x = pack_bf2(v0.x, v0.y); pk.y = pack_bf2(v0.z, v0.w);
        pk.z = pack_bf2(v1.x, v1.y); pk.w = pack_bf2(v1.z, v1.w);
        *reinterpret_cast<uint4*>(sAp + row * 1024 + ((c ^ (row & 7)) << 4)) = pk;
    }
    __syncthreads();

    // B tile fill: 2048 x 16B chunks, 4 per thread, swizzled 256B rows.
    auto fillB = [&](int u) {
        const int nt = u >> 2, kc = u & 3;
        const uint32_t dst = sB0 + (uint32_t)(u & (NBUF - 1)) * BTILE_BYTES;
        const __nv_bfloat16* src = g_cbh + (size_t)(nt * BN) * DIM + kc * BK;
#pragma unroll
        for (int i = 0; i < 4; i++) {
            const int e = tid + THREADS * i;
            const int rowb = e >> 4, c = e & 15;
            cp16(dst + rowb * 256 + ((c ^ (rowb & 7)) << 4),
                 src + (size_t)rowb * DIM + c * 8);
        }
    };

    // per-thread fragment address constants
    const int lm = lane & 15, lh = lane >> 4;
    const int arow = wm * 32 + lm;
    const int axor = arow & 7;
    const uint32_t cA0 = sA + (uint32_t)arow * 1024;
    const uint32_t cA1 = cA0 + 16u * 1024u;
    const int grp = lane >> 3, lrow = lane & 7, kpar = grp & 1;
    const int rowoff = ((grp >> 1) << 3) + lrow;

    for (int d = 0; d < depth; d++) {
        float acc[2][4][4];
#pragma unroll
        for (int mi = 0; mi < 2; mi++)
#pragma unroll
            for (int ni = 0; ni < 4; ni++)
#pragma unroll
                for (int j = 0; j < 4; j++) acc[mi][ni][j] = 0.0f;

        // per-thread running top-2 for its 4 owned rows
        float t1v[4], t2v[4]; int t1i[4], t2i[4];
#pragma unroll
        for (int r = 0; r < 4; r++) {
            t1v[r] = -3.0e38f; t2v[r] = -3.0e38f;
            t1i[r] = 0x7fffffff; t2i[r] = 0x7fffffff;
        }

        fillB(0); cp_commit();

        for (int u = 0; u < UNITS; u++) {
            const int nt = u >> 2, kc = u & 3;

            cp_wait0();           // fill(u) resident
            __syncthreads();      // all warps done with compute(u-1)
            if (u + 1 < UNITS) fillB(u + 1);
            cp_commit();

            const uint32_t sB  = sB0 + (uint32_t)(u & (NBUF - 1)) * BTILE_BYTES;
            const uint32_t cB0 = sB + (uint32_t)(wn * 32 + rowoff) * 256;
            const uint32_t cB1 = cB0 + 16u * 256u;

#pragma unroll
            for (int ks = 0; ks < 8; ks++) {
                uint32_t a0[4], a1[4], b01[4], b23[4];
                const int ck = kc * 16 + ks * 2 + lh;       // A 16B-chunk in row
                const uint32_t aoff = (uint32_t)((ck ^ axor) << 4);
                ldsm4(a0, cA0 + aoff);
                ldsm4(a1, cA1 + aoff);
                const uint32_t boff = (uint32_t)(((ks * 2 + kpar) ^ lrow) << 4);
                ldsm4(b01, cB0 + boff);
                ldsm4(b23, cB1 + boff);
                mma16816(acc[0][0], a0, b01 + 0);
                mma16816(acc[0][1], a0, b01 + 2);
                mma16816(acc[0][2], a0, b23 + 0);
                mma16816(acc[0][3], a0, b23 + 2);
                mma16816(acc[1][0], a1, b01 + 0);
                mma16816(acc[1][1], a1, b01 + 2);
                mma16816(acc[1][2], a1, b23 + 0);
                mma16816(acc[1][3], a1, b23 + 2);
            }

            if (kc == NCHUNK - 1) {
                // ---- N-tile epilogue: update per-row top-2, reset accs ----
                const int cb0 = nt * BN + wn * 32 + 2 * (lane & 3);
#pragma unroll
                for (int mi = 0; mi < 2; mi++)
#pragma unroll
                    for (int rh = 0; rh < 2; rh++) {
                        const int ri = mi * 2 + rh;
#pragma unroll
                        for (int ni = 0; ni < 4; ni++)
#pragma unroll
                            for (int j = 0; j < 2; j++) {
                                const float v = acc[mi][ni][rh * 2 + j];
                                const int  ix = cb0 + ni * 8 + j;
                                if (v > t1v[ri]) {
                                    t2v[ri] = t1v[ri]; t2i[ri] = t1i[ri];
                                    t1v[ri] = v;       t1i[ri] = ix;
                                } else if (v > t2v[ri]) {
                                    t2v[ri] = v; t2i[ri] = ix;
                                }
                            }
#pragma unroll
                        for (int ni = 0; ni < 4; ni++) {
                            acc[mi][ni][rh * 2 + 0] = 0.0f;
                            acc[mi][ni][rh * 2 + 1] = 0.0f;
                        }
                    }
            }
        }

        // ---- stash 32 candidates per row ----
#pragma unroll
        for (int mi = 0; mi < 2; mi++)
#pragma unroll
            for (int rh = 0; rh < 2; rh++) {
                const int ri  = mi * 2 + rh;
                const int row = wm * 32 + mi * 16 + rh * 8 + (lane >> 2);
                const int sb  = wn * 8 + (lane & 3) * 2;
                s_cv[row][sb]     = t1v[ri]; s_ci[row][sb]     = t1i[ri];
                s_cv[row][sb + 1] = t2v[ri]; s_ci[row][sb + 1] = t2i[ri];
            }
        __syncthreads();

        // ---- approx top-8 prefilter per row (in-place into slots 0..7) ----
        if (tid < MC) {
            float bv[8]; int bi[8];
#pragma unroll
            for (int t = 0; t < 8; t++) { bv[t] = -3.0e38f; bi[t] = 0x7fffffff; }
            for (int t = 0; t < 32; t++) {
                float v = s_cv[tid][t]; int ix = s_ci[tid][t];
                if (v > bv[7]) {
#pragma unroll
                    for (int q = 0; q < 8; q++) {
                        if (v > bv[q]) {
                            const float a = bv[q]; const int b = bi[q];
                            bv[q] = v; bi[q] = ix; v = a; ix = b;
                        }
                    }
                }
            }
#pragma unroll
            for (int t = 0; t < 8; t++) { s_cv[tid][t] = bv[t]; s_ci[tid][t] = bi[t]; }
        }
        __syncthreads();

        // ---- exact fp32 rescore of 128 rows x 8 cands (64 dots / warp) ----
        for (int i = 0; i < 64; i++) {
            const int p    = warp * 64 + i;
            const int row  = p >> 3, slot = p & 7;
            const int cand = s_ci[row][slot];
            const float4* rr = reinterpret_cast<const float4*>(g_res + (row0 + row) * DIM);
            const float4* cc = reinterpret_cast<const float4*>(cb + (size_t)cand * DIM);
            float sum = 0.0f;
#pragma unroll
            for (int q = 0; q < 4; q++) {
                const float4 a = rr[lane + 32 * q];
                const float4 b = cc[lane + 32 * q];
                sum += a.x * b.x + a.y * b.y + a.z * b.z + a.w * b.w;
            }
#pragma unroll
            for (int off = 16; off; off >>= 1)
                sum += __shfl_xor_sync(0xffffffffu, sum, off);
            if (lane == 0) s_cv[row][slot] = sum;   // exact value
        }
        __syncthreads();

        // ---- winner per row (tie: lowest index) ----
        if (tid < MC) {
            float bv = s_cv[tid][0]; int bi = s_ci[tid][0];
#pragma unroll
            for (int t = 1; t < 8; t++) {
                const float v = s_cv[tid][t]; const int ix = s_ci[tid][t];
                if (v > bv || (v == bv && ix < bi)) { bv = v; bi = ix; }
            }
            s_u[tid] = bv; s_code[tid] = bi;
        }
        __syncthreads();

        // ---- residual update (fp32 global) + bf16 A refill (8 rows/warp) ----
        for (int rr = 0; rr < MC / NWARP; rr++) {
            const int r = warp * (MC / NWARP) + rr;
            const float uv = s_u[r];
            const int code = s_code[r];
            float4* dres = reinterpret_cast<float4*>(g_res + (row0 + r) * DIM);
            const float4* cc = reinterpret_cast<const float4*>(cb + (size_t)code * DIM);
#pragma unroll
            for (int q = 0; q < 2; q++) {
                const int c = lane + 32 * q;            // 16B chunk index
                float4 v0 = dres[c * 2 + 0], v1 = dres[c * 2 + 1];
                const float4 c0 = cc[c * 2 + 0], c1 = cc[c * 2 + 1];
                v0.x -= uv * c0.x; v0.y -= uv * c0.y; v0.z -= uv * c0.z; v0.w -= uv * c0.w;
                v1.x -= uv * c1.x; v1.y -= uv * c1.y; v1.z -= uv * c1.z; v1.w -= uv * c1.w;
                dres[c * 2 + 0] = v0; dres[c * 2 + 1] = v1;
                uint4 pk;
                pk.x = pack_bf2(v0.x, v0.y); pk.y = pack_bf2(v0.z, v0.w);
                pk.z = pack_bf2(v1.x, v1.y); pk.w = pack_bf2(v1.z, v1.w);
                *reinterpret_cast<uint4*>(sAp + r * 1024 + ((c ^ (r & 7)) << 4)) = pk;
            }
        }
        __syncthreads();
    }

    // ---- output: total = x - residual_final ----
    const float4* x4 = reinterpret_cast<const float4*>(x + row0 * DIM);
    const float4* r4 = reinterpret_cast<const float4*>(g_res + row0 * DIM);
    float4* o4 = reinterpret_cast<float4*>(out + row0 * DIM);
    for (int i = tid; i < MC * DIM / 4; i += THREADS) {
        const float4 xv = x4[i];
        const float4 rv = r4[i];
        o4[i] = make_float4(xv.x - rv.x, xv.y - rv.y, xv.z - rv.z, xv.w - rv.w);
    }
}

// ---------------------------------------------------------------------------
extern "C" void kernel_launch(void* const* d_in, const int* in_sizes, int n_in,
                              void* d_out, int out_size) {
    const float* x  = (const float*)d_in[0];
    const float* cb = (const float*)d_in[1];
    const int* depth_ptr = (n_in > 2) ? (const int*)d_in[2] : nullptr;
    float* out = (float*)d_out;

    const int dyn_smem = A_BYTES + NBUF * BTILE_BYTES;   // 196608
    cudaFuncSetAttribute(rvq_mma_kernel, cudaFuncAttributeMaxDynamicSharedMemorySize,
                         dyn_smem);

    pack_cb_kernel<<<(KS * DIM / 4) / 256, 256>>>(cb);
    rvq_mma_kernel<<<NTOK / MC, THREADS, dyn_smem>>>(x, cb, depth_ptr, out);
}